// round 1
// baseline (speedup 1.0000x reference)
#include <cuda_runtime.h>

// Problem constants (fixed by setup_inputs)
#define NN 16000      // nodes
#define NE 256000     // edges
#define NT 640000     // triplets
#define NBATCH 128    // graphs
#define HD 64         // hidden
#define OUTD 32

// ---------------- device scratch (no allocation allowed) ----------------
__device__ float g_Hh[NN * HD];    // h @ W1[0:64]
__device__ float g_P[NN * HD];     // h @ W2[0:64]
__device__ float g_R1[NN * HD];    // h @ Wn1[0:64]
__device__ float g_Rr[NN * HD];    // rbf[0:N] @ W1[64:70] + b1
__device__ float g_agg[NN * HD];   // triplet scatter (only rows < N matter)
__device__ float g_Q[NN * HD];     // agg @ W2[64:128] + b2
__device__ float g_aggr[NN * HD];  // edge scatter onto nodes
__device__ float g_z[NN * HD];
__device__ float g_h[NN * HD];
__device__ int g_active[NT];
__device__ int g_cnt;
__device__ float g_pool[NBATCH * HD];
__device__ float g_gcnt[NBATCH];

__device__ __forceinline__ void red_add_v4(float* addr, float4 v) {
    asm volatile("red.global.add.v4.f32 [%0], {%1,%2,%3,%4};"
                 :: "l"(addr), "f"(v.x), "f"(v.y), "f"(v.z), "f"(v.w)
                 : "memory");
}

__device__ __forceinline__ void mac16(float4* acc, float v, const float* wrow) {
    const float4* w4 = (const float4*)wrow;
#pragma unroll
    for (int c = 0; c < 16; c++) {
        float4 w = w4[c];
        acc[c].x = fmaf(v, w.x, acc[c].x);
        acc[c].y = fmaf(v, w.y, acc[c].y);
        acc[c].z = fmaf(v, w.z, acc[c].z);
        acc[c].w = fmaf(v, w.w, acc[c].w);
    }
}

// ---------------- setup kernels ----------------
__global__ void zero_small_kernel() {
    int t = threadIdx.x;
    if (t == 0) g_cnt = 0;
    for (int i = t; i < NBATCH * HD; i += blockDim.x) g_pool[i] = 0.f;
    if (t < NBATCH) g_gcnt[t] = 0.f;
}

__global__ void compact_kernel(const int* __restrict__ j_idx) {
    int i = blockIdx.x * blockDim.x + threadIdx.x;
    if (i < NT && j_idx[i] < NN) {
        g_active[atomicAdd(&g_cnt, 1)] = i;
    }
}

__global__ void zero_layer_kernel() {
    int i = blockIdx.x * blockDim.x + threadIdx.x;
    float4 z = make_float4(0.f, 0.f, 0.f, 0.f);
    if (i < NN * HD / 4) {
        ((float4*)g_agg)[i] = z;
        ((float4*)g_aggr)[i] = z;
    }
}

// ---------------- node projections: Hh, P, R1 from h; Rr from rbf ----------------
__global__ void multiproj_kernel(const float* __restrict__ x,
                                 const float* __restrict__ rbf,
                                 const float* __restrict__ W1,
                                 const float* __restrict__ b1,
                                 const float* __restrict__ W2,
                                 const float* __restrict__ Wn1,
                                 int l, int use_x) {
    __shared__ float Ws[HD * HD];
    __shared__ float bs[HD];
    int p = blockIdx.y;
    int t = threadIdx.x;
    const float* hin = use_x ? x : g_h;
    const float* W;
    const float* in;
    float* out;
    if (p == 0)      { W = W1 + l * 76 * HD;            in = hin; out = g_Hh; }
    else if (p == 1) { W = W2 + l * 128 * HD;           in = hin; out = g_P; }
    else if (p == 2) { W = Wn1 + l * 128 * HD;          in = hin; out = g_R1; }
    else             { W = W1 + l * 76 * HD + 64 * HD;  in = rbf; out = g_Rr; }
    int nw4 = (p == 3) ? (6 * HD / 4) : (HD * HD / 4);
    for (int i = t; i < nw4; i += blockDim.x)
        ((float4*)Ws)[i] = ((const float4*)W)[i];
    if (t < HD) bs[t] = (p == 3) ? b1[l * HD + t] : 0.f;
    __syncthreads();

    int row = blockIdx.x * blockDim.x + t;
    if (row >= NN) return;

    float4 acc[16];
#pragma unroll
    for (int c = 0; c < 16; c++) acc[c] = ((float4*)bs)[c];

    if (p < 3) {
        const float4* inr = (const float4*)(in + row * HD);
#pragma unroll
        for (int k4 = 0; k4 < 16; k4++) {
            float4 iv = inr[k4];
            mac16(acc, iv.x, Ws + (k4 * 4 + 0) * HD);
            mac16(acc, iv.y, Ws + (k4 * 4 + 1) * HD);
            mac16(acc, iv.z, Ws + (k4 * 4 + 2) * HD);
            mac16(acc, iv.w, Ws + (k4 * 4 + 3) * HD);
        }
    } else {
        const float* inr = in + row * 6;
#pragma unroll
        for (int k = 0; k < 6; k++) mac16(acc, inr[k], Ws + k * HD);
    }

    float4* o4 = (float4*)(out + row * HD);
#pragma unroll
    for (int c = 0; c < 16; c++) o4[c] = acc[c];
}

// ---------------- generic [N,64]@[64,64] row-GEMM over internal buffers ----------------
// which==0: Q = agg@W + bias          (no relu)
// which==1: z = relu(R1 + aggr@W + bias)
// which==2: h = z@W + bias            (no relu)
__global__ void gemm64_kernel(int which, const float* __restrict__ W,
                              const float* __restrict__ bias) {
    __shared__ float Ws[HD * HD];
    __shared__ float bs[HD];
    int t = threadIdx.x;
    for (int i = t; i < HD * HD / 4; i += blockDim.x)
        ((float4*)Ws)[i] = ((const float4*)W)[i];
    if (t < HD) bs[t] = bias[t];
    __syncthreads();

    int row = blockIdx.x * blockDim.x + t;
    if (row >= NN) return;

    const float* in = (which == 0) ? g_agg : (which == 1) ? g_aggr : g_z;
    const float* add = (which == 1) ? g_R1 : (const float*)0;
    float* out = (which == 0) ? g_Q : (which == 1) ? g_z : g_h;

    float4 acc[16];
#pragma unroll
    for (int c = 0; c < 16; c++) acc[c] = ((float4*)bs)[c];

    const float4* inr = (const float4*)(in + row * HD);
#pragma unroll
    for (int k4 = 0; k4 < 16; k4++) {
        float4 iv = inr[k4];
        mac16(acc, iv.x, Ws + (k4 * 4 + 0) * HD);
        mac16(acc, iv.y, Ws + (k4 * 4 + 1) * HD);
        mac16(acc, iv.z, Ws + (k4 * 4 + 2) * HD);
        mac16(acc, iv.w, Ws + (k4 * 4 + 3) * HD);
    }
    if (add) {
        const float4* a4 = (const float4*)(add + row * HD);
#pragma unroll
        for (int c = 0; c < 16; c++) {
            float4 a = a4[c];
            acc[c].x += a.x; acc[c].y += a.y; acc[c].z += a.z; acc[c].w += a.w;
        }
    }
    if (which == 1) {
#pragma unroll
        for (int c = 0; c < 16; c++) {
            acc[c].x = fmaxf(acc[c].x, 0.f);
            acc[c].y = fmaxf(acc[c].y, 0.f);
            acc[c].z = fmaxf(acc[c].z, 0.f);
            acc[c].w = fmaxf(acc[c].w, 0.f);
        }
    }
    float4* o4 = (float4*)(out + row * HD);
#pragma unroll
    for (int c = 0; c < 16; c++) o4[c] = acc[c];
}

// ---------------- triplet stage: only active (j_idx < N) triplets ----------------
// em = relu(Hh[k] + Rr[j] + cbf[t]@W1c); scatter-add into g_agg[j]
__global__ void triplet_kernel(const float* __restrict__ cbf,
                               const int* __restrict__ k_idx,
                               const int* __restrict__ j_idx,
                               const float* __restrict__ W1, int l) {
    __shared__ float Wc[6 * HD];
    int t = threadIdx.x;
    const float* W1c = W1 + l * 76 * HD + 70 * HD;
    for (int i = t; i < 6 * HD / 4; i += blockDim.x)
        ((float4*)Wc)[i] = ((const float4*)W1c)[i];
    __syncthreads();

    int cnt = g_cnt;
    int lane = t & 15;
    int group = (blockIdx.x * blockDim.x + t) >> 4;
    int ngroups = (gridDim.x * blockDim.x) >> 4;
    for (int i = group; i < cnt; i += ngroups) {
        int tr = g_active[i];
        int k = k_idx[tr];
        int j = j_idx[tr];
        float4 a = ((const float4*)(g_Hh + k * HD))[lane];
        float4 b = ((const float4*)(g_Rr + j * HD))[lane];
        a.x += b.x; a.y += b.y; a.z += b.z; a.w += b.w;
        const float* cb = cbf + tr * 6;
#pragma unroll
        for (int kk = 0; kk < 6; kk++) {
            float v = cb[kk];
            float4 w = ((const float4*)(Wc + kk * HD))[lane];
            a.x = fmaf(v, w.x, a.x);
            a.y = fmaf(v, w.y, a.y);
            a.z = fmaf(v, w.z, a.z);
            a.w = fmaf(v, w.w, a.w);
        }
        a.x = fmaxf(a.x, 0.f); a.y = fmaxf(a.y, 0.f);
        a.z = fmaxf(a.z, 0.f); a.w = fmaxf(a.w, 0.f);
        red_add_v4(g_agg + j * HD + lane * 4, a);
    }
}

// ---------------- edge stage: fi = relu(P[src]+Q[dst]); scatter into aggr[dst] ----------------
__global__ void edge_kernel(const int* __restrict__ ei) {
    int t = blockIdx.x * blockDim.x + threadIdx.x;
    int lane = t & 15;
    int group = t >> 4;
    int ngroups = (gridDim.x * blockDim.x) >> 4;
    for (int e = group; e < NE; e += ngroups) {
        int s = ei[e];
        int d = ei[NE + e];
        float4 a = ((const float4*)(g_P + s * HD))[lane];
        float4 b = ((const float4*)(g_Q + d * HD))[lane];
        a.x = fmaxf(a.x + b.x, 0.f);
        a.y = fmaxf(a.y + b.y, 0.f);
        a.z = fmaxf(a.z + b.z, 0.f);
        a.w = fmaxf(a.w + b.w, 0.f);
        red_add_v4(g_aggr + d * HD + lane * 4, a);
    }
}

// ---------------- pooling ----------------
__global__ void pool_kernel(const int* __restrict__ batch) {
    int t = blockIdx.x * blockDim.x + threadIdx.x;
    int lane = t & 15;
    int n = t >> 4;
    if (n >= NN) return;
    int b = batch[n];
    float4 v = ((const float4*)(g_h + n * HD))[lane];
    red_add_v4(g_pool + b * HD + lane * 4, v);
    if (lane == 0) atomicAdd(&g_gcnt[b], 1.0f);
}

// ---------------- final small MLP ----------------
__global__ void final_kernel(const float* __restrict__ Wo1,
                             const float* __restrict__ bo1,
                             const float* __restrict__ Wo2,
                             const float* __restrict__ bo2,
                             float* __restrict__ out) {
    __shared__ float pooled[HD];
    __shared__ float t1[HD];
    int b = blockIdx.x;
    int t = threadIdx.x;  // 64 threads
    float cnt = fmaxf(g_gcnt[b], 1.0f);
    pooled[t] = fmaxf(g_pool[b * HD + t] / cnt, 0.f);
    __syncthreads();
    float acc = bo1[t];
#pragma unroll 8
    for (int k = 0; k < HD; k++) acc = fmaf(pooled[k], Wo1[k * HD + t], acc);
    t1[t] = fmaxf(acc, 0.f);
    __syncthreads();
    if (t < OUTD) {
        float a2 = bo2[t];
#pragma unroll 8
        for (int k = 0; k < HD; k++) a2 = fmaf(t1[k], Wo2[k * OUTD + t], a2);
        out[b * OUTD + t] = a2;
    }
}

// ---------------- host orchestration ----------------
extern "C" void kernel_launch(void* const* d_in, const int* in_sizes, int n_in,
                              void* d_out, int out_size) {
    (void)in_sizes; (void)n_in; (void)out_size;
    const float* x   = (const float*)d_in[0];
    const float* rbf = (const float*)d_in[1];
    const float* cbf = (const float*)d_in[2];
    const float* W1  = (const float*)d_in[3];
    const float* b1  = (const float*)d_in[4];
    const float* W2  = (const float*)d_in[5];
    const float* b2  = (const float*)d_in[6];
    const float* Wn1 = (const float*)d_in[7];
    const float* bn1 = (const float*)d_in[8];
    const float* Wn2 = (const float*)d_in[9];
    const float* bn2 = (const float*)d_in[10];
    const float* Wo1 = (const float*)d_in[11];
    const float* bo1 = (const float*)d_in[12];
    const float* Wo2 = (const float*)d_in[13];
    const float* bo2 = (const float*)d_in[14];
    const int* ei    = (const int*)d_in[15];
    const int* k_idx = (const int*)d_in[16];
    const int* j_idx = (const int*)d_in[17];
    const int* batch = (const int*)d_in[18];
    float* out = (float*)d_out;

    zero_small_kernel<<<1, 256>>>();
    compact_kernel<<<(NT + 255) / 256, 256>>>(j_idx);

    for (int l = 0; l < 3; l++) {
        zero_layer_kernel<<<(NN * HD / 4 + 255) / 256, 256>>>();
        dim3 g((NN + 127) / 128, 4);
        multiproj_kernel<<<g, 128>>>(x, rbf, W1, b1, W2, Wn1, l, (l == 0) ? 1 : 0);
        triplet_kernel<<<1024, 256>>>(cbf, k_idx, j_idx, W1, l);
        gemm64_kernel<<<(NN + 127) / 128, 128>>>(0, W2 + l * 128 * HD + 64 * HD, b2 + l * HD);
        edge_kernel<<<4096, 256>>>(ei);
        gemm64_kernel<<<(NN + 127) / 128, 128>>>(1, Wn1 + l * 128 * HD + 64 * HD, bn1 + l * HD);
        gemm64_kernel<<<(NN + 127) / 128, 128>>>(2, Wn2 + l * 64 * HD, bn2 + l * HD);
    }

    pool_kernel<<<(NN * 16 + 255) / 256, 256>>>(batch);
    final_kernel<<<NBATCH, 64>>>(Wo1, bo1, Wo2, bo2, out);
}

// round 5
// speedup vs baseline: 1.2497x; 1.2497x over previous
#include <cuda_runtime.h>

#define NN 16000      // nodes
#define NE 256000     // edges
#define NT 640000     // triplets
#define NBATCH 128    // graphs
#define HD 64         // hidden
#define OUTD 32
#define TS 68         // smem row stride (floats): 68*4=272B, 16B aligned, conflict-free

// ---------------- device scratch ----------------
__device__ float g_Hh[NN * HD];    // h @ W1[0:64]
__device__ float g_P[NN * HD];     // h @ W2[0:64]
__device__ float g_R1[NN * HD];    // h @ Wn1[0:64]
__device__ float g_Rr[NN * HD];    // rbf[0:N] @ W1[64:70] + b1
__device__ float g_agg[NN * HD];   // triplet scatter (only rows < N matter)
__device__ float g_Q[NN * HD];     // agg @ W2[64:128] + b2
__device__ float g_aggr[NN * HD];  // edge scatter onto nodes
__device__ float g_h[NN * HD];
__device__ int g_active[NT];
__device__ int g_cnt;
__device__ float g_pool[NBATCH * HD];
__device__ float g_gcnt[NBATCH];

__device__ __forceinline__ void red_add_v4(float* addr, float4 v) {
    asm volatile("red.global.add.v4.f32 [%0], {%1,%2,%3,%4};"
                 :: "l"(addr), "f"(v.x), "f"(v.y), "f"(v.z), "f"(v.w)
                 : "memory");
}

__device__ __forceinline__ void mac16(float4* acc, float v, const float* wrow) {
    const float4* w4 = (const float4*)wrow;
#pragma unroll
    for (int c = 0; c < 16; c++) {
        float4 w = w4[c];
        acc[c].x = fmaf(v, w.x, acc[c].x);
        acc[c].y = fmaf(v, w.y, acc[c].y);
        acc[c].z = fmaf(v, w.z, acc[c].z);
        acc[c].w = fmaf(v, w.w, acc[c].w);
    }
}

// ---------------- tiled GEMM building blocks ----------------
// A tile stored transposed in smem: As[k*TS + row], k,row in [0,64)
__device__ __forceinline__ void load_A_global(float* As, const float* __restrict__ A,
                                              int row0, int t) {
    int r = t >> 2;             // 0..63
    int kb = (t & 3) * 16;      // 0,16,32,48
    const float4* src = (const float4*)(A + (row0 + r) * HD + kb);
#pragma unroll
    for (int i = 0; i < 4; i++) {
        float4 v = src[i];
        int k = kb + i * 4;
        As[(k + 0) * TS + r] = v.x;
        As[(k + 1) * TS + r] = v.y;
        As[(k + 2) * TS + r] = v.z;
        As[(k + 3) * TS + r] = v.w;
    }
}

// W stored as Ws[k*TS + n] (same layout as global [64][64])
__device__ __forceinline__ void load_W(float* Ws, const float* __restrict__ W, int t) {
    int k = t >> 2;
    int nb = (t & 3) * 16;
    const float4* src = (const float4*)(W + k * HD + nb);
    float4* dst = (float4*)(Ws + k * TS + nb);
#pragma unroll
    for (int i = 0; i < 4; i++) dst[i] = src[i];
}

__device__ __forceinline__ void mm64(const float* As, const float* Ws,
                                     float4 c[4], int ri, int ci) {
#pragma unroll 8
    for (int k = 0; k < 64; k++) {
        float4 a = *(const float4*)(As + k * TS + ri * 4);
        float4 b = *(const float4*)(Ws + k * TS + ci * 4);
        c[0].x = fmaf(a.x, b.x, c[0].x); c[0].y = fmaf(a.x, b.y, c[0].y);
        c[0].z = fmaf(a.x, b.z, c[0].z); c[0].w = fmaf(a.x, b.w, c[0].w);
        c[1].x = fmaf(a.y, b.x, c[1].x); c[1].y = fmaf(a.y, b.y, c[1].y);
        c[1].z = fmaf(a.y, b.z, c[1].z); c[1].w = fmaf(a.y, b.w, c[1].w);
        c[2].x = fmaf(a.z, b.x, c[2].x); c[2].y = fmaf(a.z, b.y, c[2].y);
        c[2].z = fmaf(a.z, b.z, c[2].z); c[2].w = fmaf(a.z, b.w, c[2].w);
        c[3].x = fmaf(a.w, b.x, c[3].x); c[3].y = fmaf(a.w, b.y, c[3].y);
        c[3].z = fmaf(a.w, b.z, c[3].z); c[3].w = fmaf(a.w, b.w, c[3].w);
    }
}

// write micro-tile back into As transposed (As[col*TS + row]) for a chained GEMM
__device__ __forceinline__ void store_A_trans(float* As, const float4 c[4], int ri, int ci) {
#pragma unroll
    for (int i = 0; i < 4; i++) {
        int r = ri * 4 + i;
        As[(ci * 4 + 0) * TS + r] = c[i].x;
        As[(ci * 4 + 1) * TS + r] = c[i].y;
        As[(ci * 4 + 2) * TS + r] = c[i].z;
        As[(ci * 4 + 3) * TS + r] = c[i].w;
    }
}

// ---------------- setup kernels ----------------
__global__ void zero_small_kernel() {
    int t = threadIdx.x;
    if (t == 0) g_cnt = 0;
    for (int i = t; i < NBATCH * HD; i += blockDim.x) g_pool[i] = 0.f;
    if (t < NBATCH) g_gcnt[t] = 0.f;
}

__global__ void compact_kernel(const int* __restrict__ j_idx) {
    int i = blockIdx.x * blockDim.x + threadIdx.x;
    if (i < NT && j_idx[i] < NN) {
        g_active[atomicAdd(&g_cnt, 1)] = i;
    }
}

__global__ void zero_layer_kernel() {
    int i = blockIdx.x * blockDim.x + threadIdx.x;
    float4 z = make_float4(0.f, 0.f, 0.f, 0.f);
    if (i < NN * HD / 4) {
        ((float4*)g_agg)[i] = z;
        ((float4*)g_aggr)[i] = z;
    }
}

// ---------------- initial projection from x: Hh, P, R1 (layer 0) ----------------
__global__ void proj3_kernel(const float* __restrict__ in,
                             const float* __restrict__ Wa,
                             const float* __restrict__ Wb,
                             const float* __restrict__ Wc) {
    __shared__ float As[64 * TS];
    __shared__ float Ws[64 * TS];
    int t = threadIdx.x;
    int row0 = blockIdx.x * 64;
    load_A_global(As, in, row0, t);
    int ri = t >> 4, ci = t & 15;
    const float* Wl[3] = {Wa, Wb, Wc};
    float* Ol[3] = {g_Hh, g_P, g_R1};
    for (int s = 0; s < 3; s++) {
        __syncthreads();
        load_W(Ws, Wl[s], t);
        __syncthreads();
        float4 c[4];
        c[0] = c[1] = c[2] = c[3] = make_float4(0.f, 0.f, 0.f, 0.f);
        mm64(As, Ws, c, ri, ci);
        float* out = Ol[s];
#pragma unroll
        for (int i = 0; i < 4; i++)
            *(float4*)(out + (row0 + ri * 4 + i) * HD + ci * 4) = c[i];
    }
}

// ---------------- Q = agg @ W2b + b2 ----------------
__global__ void qproj_kernel(const float* __restrict__ W, const float* __restrict__ bias) {
    __shared__ float As[64 * TS];
    __shared__ float Ws[64 * TS];
    __shared__ float bs[HD];
    int t = threadIdx.x;
    int row0 = blockIdx.x * 64;
    load_A_global(As, g_agg, row0, t);
    load_W(Ws, W, t);
    if (t < HD) bs[t] = bias[t];
    __syncthreads();
    int ri = t >> 4, ci = t & 15;
    float4 bv = *(float4*)(bs + ci * 4);
    float4 c[4] = {bv, bv, bv, bv};
    mm64(As, Ws, c, ri, ci);
#pragma unroll
    for (int i = 0; i < 4; i++)
        *(float4*)(g_Q + (row0 + ri * 4 + i) * HD + ci * 4) = c[i];
}

// ---------------- fused node update: z -> h -> (optionally) next-layer projections ----------------
__global__ void node_update_kernel(const float* __restrict__ Wn1b, const float* __restrict__ bn1,
                                   const float* __restrict__ Wn2, const float* __restrict__ bn2,
                                   const float* __restrict__ W1a, const float* __restrict__ W2a,
                                   const float* __restrict__ Wn1a, int do_proj) {
    __shared__ float As[64 * TS];
    __shared__ float Ws[64 * TS];
    __shared__ float bs[HD];
    int t = threadIdx.x;
    int row0 = blockIdx.x * 64;
    int ri = t >> 4, ci = t & 15;

    // GEMM1: z = relu(R1 + aggr @ Wn1b + bn1)
    load_A_global(As, g_aggr, row0, t);
    load_W(Ws, Wn1b, t);
    if (t < HD) bs[t] = bn1[t];
    __syncthreads();
    float4 bv = *(float4*)(bs + ci * 4);
    float4 c[4] = {bv, bv, bv, bv};
    mm64(As, Ws, c, ri, ci);
#pragma unroll
    for (int i = 0; i < 4; i++) {
        float4 r = *(const float4*)(g_R1 + (row0 + ri * 4 + i) * HD + ci * 4);
        c[i].x = fmaxf(c[i].x + r.x, 0.f);
        c[i].y = fmaxf(c[i].y + r.y, 0.f);
        c[i].z = fmaxf(c[i].z + r.z, 0.f);
        c[i].w = fmaxf(c[i].w + r.w, 0.f);
    }
    __syncthreads();                 // all reads of As/Ws done
    store_A_trans(As, c, ri, ci);    // As = z
    load_W(Ws, Wn2, t);
    if (t < HD) bs[t] = bn2[t];
    __syncthreads();

    // GEMM2: h = z @ Wn2 + bn2
    bv = *(float4*)(bs + ci * 4);
    c[0] = c[1] = c[2] = c[3] = bv;
    mm64(As, Ws, c, ri, ci);
#pragma unroll
    for (int i = 0; i < 4; i++)
        *(float4*)(g_h + (row0 + ri * 4 + i) * HD + ci * 4) = c[i];

    if (!do_proj) return;

    __syncthreads();                 // GEMM2 reads of As/Ws done
    store_A_trans(As, c, ri, ci);    // As = h
    const float* Wl[3] = {W1a, W2a, Wn1a};
    float* Ol[3] = {g_Hh, g_P, g_R1};
    for (int s = 0; s < 3; s++) {
        load_W(Ws, Wl[s], t);
        __syncthreads();
        float4 d[4];
        d[0] = d[1] = d[2] = d[3] = make_float4(0.f, 0.f, 0.f, 0.f);
        mm64(As, Ws, d, ri, ci);
        float* out = Ol[s];
#pragma unroll
        for (int i = 0; i < 4; i++)
            *(float4*)(out + (row0 + ri * 4 + i) * HD + ci * 4) = d[i];
        __syncthreads();             // before next load_W overwrites Ws
    }
}

// ---------------- Rr = rbf[0:N] @ W1[64:70] + b1 (K=6, row-per-thread) ----------------
__global__ void rbfproj_kernel(const float* __restrict__ rbf,
                               const float* __restrict__ W1,
                               const float* __restrict__ b1, int l) {
    __shared__ float Wc[6 * HD];
    __shared__ float bs[HD];
    int t = threadIdx.x;
    const float* W = W1 + l * 76 * HD + 64 * HD;
    for (int i = t; i < 6 * HD / 4; i += blockDim.x)
        ((float4*)Wc)[i] = ((const float4*)W)[i];
    if (t < HD) bs[t] = b1[l * HD + t];
    __syncthreads();
    int row = blockIdx.x * blockDim.x + t;
    if (row >= NN) return;
    float4 acc[16];
#pragma unroll
    for (int c = 0; c < 16; c++) acc[c] = ((float4*)bs)[c];
    const float* r = rbf + row * 6;
#pragma unroll
    for (int k = 0; k < 6; k++) mac16(acc, r[k], Wc + k * HD);
    float4* o4 = (float4*)(g_Rr + row * HD);
#pragma unroll
    for (int c = 0; c < 16; c++) o4[c] = acc[c];
}

// ---------------- triplet stage: only active (j_idx < N) triplets ----------------
__global__ void triplet_kernel(const float* __restrict__ cbf,
                               const int* __restrict__ k_idx,
                               const int* __restrict__ j_idx,
                               const float* __restrict__ W1, int l) {
    __shared__ float Wc[6 * HD];
    int t = threadIdx.x;
    const float* W1c = W1 + l * 76 * HD + 70 * HD;
    for (int i = t; i < 6 * HD / 4; i += blockDim.x)
        ((float4*)Wc)[i] = ((const float4*)W1c)[i];
    __syncthreads();

    int cnt = g_cnt;
    int lane = t & 15;
    int group = (blockIdx.x * blockDim.x + t) >> 4;
    int ngroups = (gridDim.x * blockDim.x) >> 4;
    for (int i = group; i < cnt; i += ngroups) {
        int tr = g_active[i];
        int k = k_idx[tr];
        int j = j_idx[tr];
        float4 a = ((const float4*)(g_Hh + k * HD))[lane];
        float4 b = ((const float4*)(g_Rr + j * HD))[lane];
        a.x += b.x; a.y += b.y; a.z += b.z; a.w += b.w;
        const float* cb = cbf + tr * 6;
#pragma unroll
        for (int kk = 0; kk < 6; kk++) {
            float v = cb[kk];
            float4 w = ((const float4*)(Wc + kk * HD))[lane];
            a.x = fmaf(v, w.x, a.x);
            a.y = fmaf(v, w.y, a.y);
            a.z = fmaf(v, w.z, a.z);
            a.w = fmaf(v, w.w, a.w);
        }
        a.x = fmaxf(a.x, 0.f); a.y = fmaxf(a.y, 0.f);
        a.z = fmaxf(a.z, 0.f); a.w = fmaxf(a.w, 0.f);
        red_add_v4(g_agg + j * HD + lane * 4, a);
    }
}

// ---------------- edge stage: fi = relu(P[src]+Q[dst]); scatter into aggr[dst] ----------------
__global__ void edge_kernel(const int* __restrict__ ei) {
    int t = blockIdx.x * blockDim.x + threadIdx.x;
    int lane = t & 15;
    int group = t >> 4;
    int ngroups = (gridDim.x * blockDim.x) >> 4;
    for (int e = group; e < NE; e += ngroups) {
        int s = ei[e];
        int d = ei[NE + e];
        float4 a = ((const float4*)(g_P + s * HD))[lane];
        float4 b = ((const float4*)(g_Q + d * HD))[lane];
        a.x = fmaxf(a.x + b.x, 0.f);
        a.y = fmaxf(a.y + b.y, 0.f);
        a.z = fmaxf(a.z + b.z, 0.f);
        a.w = fmaxf(a.w + b.w, 0.f);
        red_add_v4(g_aggr + d * HD + lane * 4, a);
    }
}

// ---------------- pooling ----------------
__global__ void pool_kernel(const int* __restrict__ batch) {
    int t = blockIdx.x * blockDim.x + threadIdx.x;
    int lane = t & 15;
    int n = t >> 4;
    if (n >= NN) return;
    int b = batch[n];
    float4 v = ((const float4*)(g_h + n * HD))[lane];
    red_add_v4(g_pool + b * HD + lane * 4, v);
    if (lane == 0) atomicAdd(&g_gcnt[b], 1.0f);
}

// ---------------- final small MLP ----------------
__global__ void final_kernel(const float* __restrict__ Wo1,
                             const float* __restrict__ bo1,
                             const float* __restrict__ Wo2,
                             const float* __restrict__ bo2,
                             float* __restrict__ out) {
    __shared__ float pooled[HD];
    __shared__ float t1[HD];
    int b = blockIdx.x;
    int t = threadIdx.x;  // 64 threads
    float cnt = fmaxf(g_gcnt[b], 1.0f);
    pooled[t] = fmaxf(g_pool[b * HD + t] / cnt, 0.f);
    __syncthreads();
    float acc = bo1[t];
#pragma unroll 8
    for (int k = 0; k < HD; k++) acc = fmaf(pooled[k], Wo1[k * HD + t], acc);
    t1[t] = fmaxf(acc, 0.f);
    __syncthreads();
    if (t < OUTD) {
        float a2 = bo2[t];
#pragma unroll 8
        for (int k = 0; k < HD; k++) a2 = fmaf(t1[k], Wo2[k * OUTD + t], a2);
        out[b * OUTD + t] = a2;
    }
}

// ---------------- host orchestration ----------------
extern "C" void kernel_launch(void* const* d_in, const int* in_sizes, int n_in,
                              void* d_out, int out_size) {
    (void)in_sizes; (void)n_in; (void)out_size;
    const float* x   = (const float*)d_in[0];
    const float* rbf = (const float*)d_in[1];
    const float* cbf = (const float*)d_in[2];
    const float* W1  = (const float*)d_in[3];
    const float* b1  = (const float*)d_in[4];
    const float* W2  = (const float*)d_in[5];
    const float* b2  = (const float*)d_in[6];
    const float* Wn1 = (const float*)d_in[7];
    const float* bn1 = (const float*)d_in[8];
    const float* Wn2 = (const float*)d_in[9];
    const float* bn2 = (const float*)d_in[10];
    const float* Wo1 = (const float*)d_in[11];
    const float* bo1 = (const float*)d_in[12];
    const float* Wo2 = (const float*)d_in[13];
    const float* bo2 = (const float*)d_in[14];
    const int* ei    = (const int*)d_in[15];
    const int* k_idx = (const int*)d_in[16];
    const int* j_idx = (const int*)d_in[17];
    const int* batch = (const int*)d_in[18];
    float* out = (float*)d_out;

    zero_small_kernel<<<1, 256>>>();
    compact_kernel<<<(NT + 255) / 256, 256>>>(j_idx);
    proj3_kernel<<<NN / 64, 256>>>(x, W1, W2, Wn1);

    for (int l = 0; l < 3; l++) {
        rbfproj_kernel<<<(NN + 255) / 256, 256>>>(rbf, W1, b1, l);
        zero_layer_kernel<<<(NN * HD / 4 + 255) / 256, 256>>>();
        triplet_kernel<<<1024, 256>>>(cbf, k_idx, j_idx, W1, l);
        qproj_kernel<<<NN / 64, 256>>>(W2 + l * 128 * HD + 64 * HD, b2 + l * HD);
        edge_kernel<<<4096, 256>>>(ei);
        int nl = (l < 2) ? (l + 1) : l;   // next-layer weights (unused when do_proj=0)
        node_update_kernel<<<NN / 64, 256>>>(
            Wn1 + l * 128 * HD + 64 * HD, bn1 + l * HD,
            Wn2 + l * 64 * HD, bn2 + l * HD,
            W1 + nl * 76 * HD, W2 + nl * 128 * HD, Wn1 + nl * 128 * HD,
            (l < 2) ? 1 : 0);
    }

    pool_kernel<<<(NN * 16 + 255) / 256, 256>>>(batch);
    final_kernel<<<NBATCH, 64>>>(Wo1, bo1, Wo2, bo2, out);
}